// round 5
// baseline (speedup 1.0000x reference)
#include <cuda_runtime.h>
#include <cuda_bf16.h>
#include <cstdint>

// ContinuousEmbedding: out[b,f,:] = sum_k weight[k,:] / (|idx(x[b,f]) - k| + 1)
// Collapses to a 64x64 lookup table T (16 KB) indexed by bucket index.
//
// R5: single fused kernel. Each block builds T in shared memory (cheap: one
// reciprocal per (r,k), warp-broadcast weight reads), then warps stream
// 32-row tiles with EXPLICIT 8-deep register batching (v[8]) so stores have
// real MLP — R3's regs=32 showed ptxas serialized the 16-iter fan-out.

#define NUM_BINS 63
#define KDIM 64          // NUM_BINS + 1
#define EMB_DIM 64

__global__ void __launch_bounds__(256, 4)
fused_embed(const float* __restrict__ x,
            const float* __restrict__ low,     // [64]; low[0]=-inf, bins=low[1..]
            const float* __restrict__ weight,  // [64*64]
            float4* __restrict__ out,
            int n_rows)
{
    __shared__ float sT[KDIM * EMB_DIM];       // 16 KB: weight, then table (in place)
    float4* s4 = reinterpret_cast<float4*>(sT);
    const int tid = threadIdx.x;

    // ---- stage weight into shared ----------------------------------------
    const float4* w4 = reinterpret_cast<const float4*>(weight);
#pragma unroll
    for (int i = tid; i < KDIM * EMB_DIM / 4; i += 256)
        s4[i] = __ldg(w4 + i);
    __syncthreads();

    // ---- build table in place: thread -> (r = tid&63, dgroup = tid>>6) ----
    // T[r, dg*16 + i] = sum_k w[k, dg*16+i] / (|r-k|+1)
    // Weight reads are lane-uniform within a warp (address independent of r)
    // -> smem broadcast, essentially free. One reciprocal per k.
    {
        const int r  = tid & 63;
        const int dg = tid >> 6;               // 0..3
        float acc[16];
#pragma unroll
        for (int i = 0; i < 16; ++i) acc[i] = 0.0f;

#pragma unroll 8
        for (int k = 0; k < KDIM; ++k) {
            int diff = r - k; if (diff < 0) diff = -diff;
            const float s = 1.0f / (float)(diff + 1);
            const float4 a0 = s4[k * 16 + dg * 4 + 0];
            const float4 a1 = s4[k * 16 + dg * 4 + 1];
            const float4 a2 = s4[k * 16 + dg * 4 + 2];
            const float4 a3 = s4[k * 16 + dg * 4 + 3];
            acc[ 0] = fmaf(a0.x, s, acc[ 0]); acc[ 1] = fmaf(a0.y, s, acc[ 1]);
            acc[ 2] = fmaf(a0.z, s, acc[ 2]); acc[ 3] = fmaf(a0.w, s, acc[ 3]);
            acc[ 4] = fmaf(a1.x, s, acc[ 4]); acc[ 5] = fmaf(a1.y, s, acc[ 5]);
            acc[ 6] = fmaf(a1.z, s, acc[ 6]); acc[ 7] = fmaf(a1.w, s, acc[ 7]);
            acc[ 8] = fmaf(a2.x, s, acc[ 8]); acc[ 9] = fmaf(a2.y, s, acc[ 9]);
            acc[10] = fmaf(a2.z, s, acc[10]); acc[11] = fmaf(a2.w, s, acc[11]);
            acc[12] = fmaf(a3.x, s, acc[12]); acc[13] = fmaf(a3.y, s, acc[13]);
            acc[14] = fmaf(a3.z, s, acc[14]); acc[15] = fmaf(a3.w, s, acc[15]);
        }
        __syncthreads();                       // all weight reads complete

#pragma unroll
        for (int j = 0; j < 4; ++j)
            s4[r * 16 + dg * 4 + j] =
                make_float4(acc[4*j], acc[4*j+1], acc[4*j+2], acc[4*j+3]);
        __syncthreads();                       // table ready
    }

    // ---- streaming fan-out: 32-row tiles per warp, 8-deep batches ---------
    const int lane = tid & 31;
    const int warp = tid >> 5;
    const int half = lane >> 4;                // row-within-pair
    const int part = lane & 15;                // float4 slot within a row
    const int gw = blockIdx.x * 8 + warp;
    const int nw = gridDim.x * 8;
    const float4* sT4 = reinterpret_cast<const float4*>(sT);

    for (int base = gw * 32; base < n_rows; base += nw * 32) {
        // bucket index for row base+lane: g = #{ j : bins[j] < x }
        // arithmetic guess (bins ~ linspace step 0.1) + EXACT fixup
        int g = 0;
        const int xrow = base + lane;
        if (xrow < n_rows) {
            const float xv = __ldg(x + xrow);
            g = (int)floorf((xv + 3.1f) * 10.0f) + 1;
            g = max(0, min(NUM_BINS, g));
            while (g > 0 && !(xv > __ldg(low + g))) --g;      // bins[g-1]==low[g]
            while (g < NUM_BINS && (xv > __ldg(low + g + 1))) ++g;
        }

#pragma unroll
        for (int h = 0; h < 2; ++h) {
            int    idxs[8];
            float4 v[8];
#pragma unroll
            for (int j = 0; j < 8; ++j)
                idxs[j] = __shfl_sync(0xffffffffu, g, (h * 8 + j) * 2 + half);
#pragma unroll
            for (int j = 0; j < 8; ++j)
                v[j] = sT4[(idxs[j] << 4) + part];
#pragma unroll
            for (int j = 0; j < 8; ++j) {
                const int r = base + (h * 8 + j) * 2 + half;
                if (r < n_rows)
                    __stcs(&out[(size_t)r * 16 + part], v[j]);
            }
        }
    }
}

extern "C" void kernel_launch(void* const* d_in, const int* in_sizes, int n_in,
                              void* d_out, int out_size) {
    const float* x      = (const float*)d_in[0];   // [B*F]
    const float* low    = (const float*)d_in[1];   // [64]
    // d_in[2] = high [64] (redundant with low for the bucket computation)
    const float* weight = (const float*)d_in[3];   // [64*64]

    float4* out = (float4*)d_out;
    const int n_rows = out_size / EMB_DIM;         // 524288

    // 592 blocks = 4 resident blocks x 148 SMs: single wave, grid-stride.
    int blocks = 592;
    int n_tiles = (n_rows + 31) / 32;
    int max_blocks = (n_tiles + 7) / 8;
    if (blocks > max_blocks) blocks = max_blocks;
    if (blocks < 1) blocks = 1;

    fused_embed<<<blocks, 256>>>(x, low, weight, out, n_rows);
}

// round 6
// speedup vs baseline: 1.1221x; 1.1221x over previous
#include <cuda_runtime.h>
#include <cuda_bf16.h>
#include <cstdint>

// ContinuousEmbedding: out[b,f,:] = sum_k weight[k,:] / (|idx(x[b,f]) - k| + 1)
// Collapses to a 64x64 lookup table T (16 KB) indexed by bucket index.
//
// R6: single fused kernel, 296 blocks x 512 threads (2/SM). Each block builds
// T in shared once (cheap at this block size: warp-uniform LDS + 8 FMA per
// k-step per thread, ~1.5us), then 16 warps/block stream 32-row output tiles
// with explicit 8-deep register batching (shfl batch -> LDS batch -> STG
// batch) so the store path has real MLP.

#define NUM_BINS 63
#define KDIM 64          // NUM_BINS + 1
#define EMB_DIM 64

__global__ void __launch_bounds__(512, 2)
fused_embed(const float* __restrict__ x,
            const float* __restrict__ low,     // [64]; low[0]=-inf, bins=low[1..]
            const float* __restrict__ weight,  // [64*64]
            float4* __restrict__ out,
            int n_rows)
{
    __shared__ float  sT[KDIM * EMB_DIM];      // 16 KB: weight, then table (in place)
    __shared__ float  sb[NUM_BINS];            // bin boundaries
    float4* s4 = reinterpret_cast<float4*>(sT);
    const int tid = threadIdx.x;

    // ---- stage weight into shared (1024 float4 / 512 thr = 2 each) -------
    const float4* w4 = reinterpret_cast<const float4*>(weight);
#pragma unroll
    for (int i = tid; i < KDIM * EMB_DIM / 4; i += 512)
        s4[i] = __ldg(w4 + i);
    if (tid < NUM_BINS)
        sb[tid] = __ldg(low + tid + 1);
    __syncthreads();

    // ---- build table in place -------------------------------------------
    // thread -> (r = tid&63, dp = tid>>6 in 0..7); computes 2 float4 =
    // T[r, dp*8 .. dp*8+7]. Weight reads are warp-uniform (dp constant
    // within a warp) -> smem broadcast. 64 iters x (2 uniform LDS + 8 FMA).
    {
        const int r  = tid & 63;
        const int dp = tid >> 6;               // 0..7
        float acc[8];
#pragma unroll
        for (int i = 0; i < 8; ++i) acc[i] = 0.0f;

#pragma unroll 8
        for (int k = 0; k < KDIM; ++k) {
            int diff = r - k; if (diff < 0) diff = -diff;
            const float s = 1.0f / (float)(diff + 1);
            const float4 a0 = s4[k * 16 + dp * 2 + 0];
            const float4 a1 = s4[k * 16 + dp * 2 + 1];
            acc[0] = fmaf(a0.x, s, acc[0]); acc[1] = fmaf(a0.y, s, acc[1]);
            acc[2] = fmaf(a0.z, s, acc[2]); acc[3] = fmaf(a0.w, s, acc[3]);
            acc[4] = fmaf(a1.x, s, acc[4]); acc[5] = fmaf(a1.y, s, acc[5]);
            acc[6] = fmaf(a1.z, s, acc[6]); acc[7] = fmaf(a1.w, s, acc[7]);
        }
        __syncthreads();                       // all weight reads complete

        s4[(r << 4) + dp * 2 + 0] = make_float4(acc[0], acc[1], acc[2], acc[3]);
        s4[(r << 4) + dp * 2 + 1] = make_float4(acc[4], acc[5], acc[6], acc[7]);
        __syncthreads();                       // table ready
    }

    // ---- streaming fan-out: 32-row tiles per warp, 8-deep batches ---------
    const int lane = tid & 31;
    const int warp = tid >> 5;                 // 0..15
    const int half = lane >> 4;                // row-within-pair
    const int part = lane & 15;                // float4 slot within a row
    const int gw = blockIdx.x * 16 + warp;
    const int nw = gridDim.x * 16;
    const float4* sT4 = reinterpret_cast<const float4*>(sT);

    for (int base = gw * 32; base < n_rows; base += nw * 32) {
        // bucket index for row base+lane: g = #{ j : bins[j] < x }
        // arithmetic guess (bins ~ linspace(-3.1,3.1,63)) + EXACT fixup
        int g = 0;
        const int xrow = base + lane;
        if (xrow < n_rows) {
            const float xv = __ldg(x + xrow);
            g = (int)floorf((xv + 3.1f) * 10.0f) + 1;
            g = max(0, min(NUM_BINS, g));
            while (g > 0 && !(xv > sb[g - 1])) --g;
            while (g < NUM_BINS && (xv > sb[g])) ++g;
        }

#pragma unroll
        for (int h = 0; h < 2; ++h) {
            int    idxs[8];
            float4 v[8];
#pragma unroll
            for (int j = 0; j < 8; ++j)
                idxs[j] = __shfl_sync(0xffffffffu, g, (h * 8 + j) * 2 + half);
#pragma unroll
            for (int j = 0; j < 8; ++j)
                v[j] = sT4[(idxs[j] << 4) + part];
#pragma unroll
            for (int j = 0; j < 8; ++j) {
                const int r = base + (h * 8 + j) * 2 + half;
                if (r < n_rows)
                    __stcs(&out[(size_t)r * 16 + part], v[j]);
            }
        }
    }
}

extern "C" void kernel_launch(void* const* d_in, const int* in_sizes, int n_in,
                              void* d_out, int out_size) {
    const float* x      = (const float*)d_in[0];   // [B*F]
    const float* low    = (const float*)d_in[1];   // [64]
    // d_in[2] = high [64] (redundant with low for the bucket computation)
    const float* weight = (const float*)d_in[3];   // [64*64]

    float4* out = (float4*)d_out;
    const int n_rows = out_size / EMB_DIM;         // 524288

    // 296 blocks = 2 resident blocks x 148 SMs, grid-stride over 32-row tiles.
    int blocks = 296;
    int n_tiles = (n_rows + 31) / 32;
    int max_blocks = (n_tiles + 15) / 16;
    if (blocks > max_blocks) blocks = max_blocks;
    if (blocks < 1) blocks = 1;

    fused_embed<<<blocks, 512>>>(x, low, weight, out, n_rows);
}